// round 9
// baseline (speedup 1.0000x reference)
#include <cuda_runtime.h>
#include <cuda_bf16.h>
#include <cuda_fp16.h>
#include <cstdint>

#define N_NODES 50000
#define N_EDGES 600000
#define LN_EPS 1e-5f
#define NT 391            // ceil(50000/128) M-tiles
#define NROWS_PAD (NT * 128)   // 50048
#define GEMM_GRID 148
#define SCAN_BLOCKS 196   // ceil(50000/256)

// smem word layout for GEMM (uint32 units); A/B rows padded to 68 words (136 bf16)
#define ROWW 68
#define SA_HI 0
#define SA_LO 8704
#define SB_HI 17408
#define SB_LO 26112
#define GEMM_SMEM_WORDS 34816
#define GEMM_SMEM_BYTES (GEMM_SMEM_WORDS * 4)

// ---------------- device scratch ----------------
__device__ __align__(16) __half g_hh[N_NODES * 128];        // GEMM output, fp16
__device__ __align__(16) uint32_t g_ah[NROWS_PAD * 64];     // layer-1 act, bf16 hi (64 u32/row)
__device__ __align__(16) uint32_t g_al[NROWS_PAD * 64];     // layer-1 act, bf16 lo
__device__ float g_dinv[N_NODES];
__device__ __align__(16) int g_cnt[N_NODES];   // zero at load; k_fill re-zeros each run
__device__ int   g_rowstart[N_NODES + 1];
__device__ int   g_cur[N_NODES];
__device__ int   g_csrsrc[N_EDGES];
// bf16 W^T images (B layout: [n][k], linear): [layer][hi/lo]
__device__ __align__(16) uint4 g_wimg[2][2][2048];

// ---------------- CSR build ----------------
// 8 edges per thread, loads issued before the 8 non-returning REDs
__global__ void k_count(const int* __restrict__ ei) {
    int i = blockIdx.x * blockDim.x + threadIdx.x;
    const int4* D = (const int4*)(ei + N_EDGES);
    const int HALF = N_EDGES / 8;   // 75000 int4 per half
    if (i < HALF) {
        int4 d0 = D[i];
        int4 d1 = D[i + HALF];
        atomicAdd(&g_cnt[d0.x], 1);
        atomicAdd(&g_cnt[d0.y], 1);
        atomicAdd(&g_cnt[d0.z], 1);
        atomicAdd(&g_cnt[d0.w], 1);
        atomicAdd(&g_cnt[d1.x], 1);
        atomicAdd(&g_cnt[d1.y], 1);
        atomicAdd(&g_cnt[d1.z], 1);
        atomicAdd(&g_cnt[d1.w], 1);
    }
}

// single scan kernel: each block re-sums its prefix straight from g_cnt (L2-resident)
__global__ void k_scan() {
    __shared__ int wsum[8];
    int t = threadIdx.x, lane = t & 31, w = t >> 5;

    // cross-block offset = sum g_cnt[0 .. bid*256)
    const int4* C4 = (const int4*)g_cnt;
    int npre = blockIdx.x * 64;     // int4 count before this block
    int pre = 0;
    for (int j = t; j < npre; j += 256) {
        int4 v = C4[j];
        pre += v.x + v.y + v.z + v.w;
    }
#pragma unroll
    for (int o = 16; o; o >>= 1) pre += __shfl_xor_sync(0xffffffffu, pre, o);
    if (lane == 0) wsum[w] = pre;
    __syncthreads();
    int blockoff = 0;
#pragma unroll
    for (int j = 0; j < 8; j++) blockoff += wsum[j];
    __syncthreads();

    // intra-block inclusive scan (warp shuffle + warp offsets)
    int i = blockIdx.x * 256 + t;
    int c = (i < N_NODES) ? g_cnt[i] : 0;
    int v = c;
#pragma unroll
    for (int o = 1; o < 32; o <<= 1) {
        int n = __shfl_up_sync(0xffffffffu, v, o);
        if (lane >= o) v += n;
    }
    if (lane == 31) wsum[w] = v;
    __syncthreads();
    int woff = 0;
#pragma unroll
    for (int j = 0; j < 8; j++)
        if (j < w) woff += wsum[j];

    if (i < N_NODES) {
        int excl = blockoff + woff + v - c;
        g_rowstart[i] = excl;
        g_cur[i] = excl;
        g_dinv[i] = rsqrtf((float)c + 1.0f);
    }
    if (blockIdx.x == SCAN_BLOCKS - 1 && t == 255)
        g_rowstart[N_NODES] = blockoff + woff + v;
}

// fill CSR; also re-zeros g_cnt for the next replay (fill never reads g_cnt)
__global__ void k_fill(const int* __restrict__ ei) {
    int i = blockIdx.x * blockDim.x + threadIdx.x;
    if (i < N_NODES / 4) ((int4*)g_cnt)[i] = make_int4(0, 0, 0, 0);
    const int4* S = (const int4*)ei;
    const int4* D = (const int4*)(ei + N_EDGES);
    const int HALF = N_EDGES / 8;
    if (i < HALF) {
        int4 s0 = S[i];
        int4 d0 = D[i];
        int4 s1 = S[i + HALF];
        int4 d1 = D[i + HALF];
        g_csrsrc[atomicAdd(&g_cur[d0.x], 1)] = s0.x;
        g_csrsrc[atomicAdd(&g_cur[d0.y], 1)] = s0.y;
        g_csrsrc[atomicAdd(&g_cur[d0.z], 1)] = s0.z;
        g_csrsrc[atomicAdd(&g_cur[d0.w], 1)] = s0.w;
        g_csrsrc[atomicAdd(&g_cur[d1.x], 1)] = s1.x;
        g_csrsrc[atomicAdd(&g_cur[d1.y], 1)] = s1.y;
        g_csrsrc[atomicAdd(&g_cur[d1.z], 1)] = s1.z;
        g_csrsrc[atomicAdd(&g_cur[d1.w], 1)] = s1.w;
    }
}

// ---------------- W -> transposed bf16 hi/lo images + split-image tail pad ----------------
__global__ void k_convW(const float* __restrict__ W1, const float* __restrict__ W2) {
    int layer = blockIdx.y;
    const float* W = layer ? W2 : W1;
    __nv_bfloat16* hi = (__nv_bfloat16*)g_wimg[layer][0];
    __nv_bfloat16* lo = (__nv_bfloat16*)g_wimg[layer][1];
    for (int i = blockIdx.x * blockDim.x + threadIdx.x; i < 16384; i += blockDim.x * gridDim.x) {
        int n = i >> 7, k = i & 127;          // B[n][k] = W[k][n]
        float w = W[k * 128 + n];
        __nv_bfloat16 h = __float2bfloat16(w);
        __nv_bfloat16 l = __float2bfloat16(w - __bfloat162float(h));
        hi[n * 128 + k] = h;
        lo[n * 128 + k] = l;
    }
    // zero-pad tail rows of the split activation images (rows 50000..50047)
    if (layer == 0) {
        int base = N_NODES * 64;
        int total = (NROWS_PAD - N_NODES) * 64;   // 3072
        for (int i = blockIdx.x * blockDim.x + threadIdx.x; i < total;
             i += blockDim.x * gridDim.x / 2) {
            g_ah[base + i] = 0;
            g_al[base + i] = 0;
        }
    }
}

// ---------------- mma.sync bf16 split-precision GEMM ----------------
__device__ __forceinline__ uint32_t pack2(__nv_bfloat16 a, __nv_bfloat16 b) {
    return (uint32_t)__bfloat16_as_ushort(a) | ((uint32_t)__bfloat16_as_ushort(b) << 16);
}

__device__ __forceinline__ void mma_bf16(float* c, const uint32_t* a, const uint32_t* b) {
    asm volatile(
        "mma.sync.aligned.m16n8k16.row.col.f32.bf16.bf16.f32 "
        "{%0,%1,%2,%3}, {%4,%5,%6,%7}, {%8,%9}, {%0,%1,%2,%3};"
        : "+f"(c[0]), "+f"(c[1]), "+f"(c[2]), "+f"(c[3])
        : "r"(a[0]), "r"(a[1]), "r"(a[2]), "r"(a[3]), "r"(b[0]), "r"(b[1]));
}

// H = X @ W via D = Ah*Bh + Ah*Bl + Al*Bh; persistent CTAs over M-tiles of 128.
// layer 0: A from fp32 Xin (convert). layer 1: A from pre-split g_ah/g_al (copy).
__global__ void __launch_bounds__(256, 1) k_gemm_mma(const float* __restrict__ Xin, int layer) {
    extern __shared__ uint32_t sw[];
    uint32_t* sAh = sw + SA_HI;
    uint32_t* sAl = sw + SA_LO;
    uint32_t* sBh = sw + SB_HI;
    uint32_t* sBl = sw + SB_LO;

    const float4* X4 = (const float4*)Xin;
    int tid = threadIdx.x, wid = tid >> 5, lane = tid & 31;
    int g = lane >> 2, t = lane & 3;
    int wm = wid & 3, wn = wid >> 2;

    // stage B (W^T) hi/lo into padded smem, once
    {
        const uint4* Bh = g_wimg[layer][0];
        const uint4* Bl = g_wimg[layer][1];
#pragma unroll 4
        for (int i = tid; i < 2048; i += 256) {
            int n = i >> 4, kc = i & 15;
            *(uint4*)(sBh + n * ROWW + kc * 4) = Bh[i];
            *(uint4*)(sBl + n * ROWW + kc * 4) = Bl[i];
        }
    }
    __syncthreads();

    for (int tile = blockIdx.x; tile < NT; tile += gridDim.x) {
        int rowBase = tile * 128;

        if (layer == 0) {
            // convert A tile fp32 -> bf16 hi/lo into padded smem
#pragma unroll 4
            for (int i = tid; i < 4096; i += 256) {      // 128 rows x 32 float4
                int r = i >> 5, c = i & 31;
                int grow = rowBase + r;
                float4 v = (grow < N_NODES) ? X4[grow * 32 + c] : make_float4(0.f, 0.f, 0.f, 0.f);
                __nv_bfloat16 h0 = __float2bfloat16(v.x), h1 = __float2bfloat16(v.y);
                __nv_bfloat16 h2 = __float2bfloat16(v.z), h3 = __float2bfloat16(v.w);
                __nv_bfloat16 l0 = __float2bfloat16(v.x - __bfloat162float(h0));
                __nv_bfloat16 l1 = __float2bfloat16(v.y - __bfloat162float(h1));
                __nv_bfloat16 l2 = __float2bfloat16(v.z - __bfloat162float(h2));
                __nv_bfloat16 l3 = __float2bfloat16(v.w - __bfloat162float(h3));
                *(uint2*)(sAh + r * ROWW + c * 2) = make_uint2(pack2(h0, h1), pack2(h2, h3));
                *(uint2*)(sAl + r * ROWW + c * 2) = make_uint2(pack2(l0, l1), pack2(l2, l3));
            }
        } else {
            // copy pre-split A tile (bf16 hi/lo) into padded smem: 128 rows x 16 uint4
#pragma unroll 4
            for (int i = tid; i < 2048; i += 256) {
                int r = i >> 4, q = i & 15;
                int gi = (rowBase + r) * 16 + q;         // uint4 index (row stride 16)
                *(uint4*)(sAh + r * ROWW + q * 4) = ((const uint4*)g_ah)[gi];
                *(uint4*)(sAl + r * ROWW + q * 4) = ((const uint4*)g_al)[gi];
            }
        }
        __syncthreads();

        float acc[2][8][4];
#pragma unroll
        for (int mi = 0; mi < 2; mi++)
#pragma unroll
            for (int ni = 0; ni < 8; ni++)
#pragma unroll
                for (int j = 0; j < 4; j++) acc[mi][ni][j] = 0.0f;

#pragma unroll
        for (int ks = 0; ks < 8; ks++) {
            int kw = ks * 8;
            uint32_t ah[2][4], al[2][4];
#pragma unroll
            for (int mi = 0; mi < 2; mi++) {
                int r0 = (wm * 32 + mi * 16 + g) * ROWW + kw + t;
                int r1 = r0 + 8 * ROWW;
                ah[mi][0] = sAh[r0]; ah[mi][1] = sAh[r1];
                ah[mi][2] = sAh[r0 + 4]; ah[mi][3] = sAh[r1 + 4];
                al[mi][0] = sAl[r0]; al[mi][1] = sAl[r1];
                al[mi][2] = sAl[r0 + 4]; al[mi][3] = sAl[r1 + 4];
            }
            uint32_t bh[8][2], bl[8][2];
#pragma unroll
            for (int ni = 0; ni < 8; ni++) {
                int nb = (wn * 64 + ni * 8 + g) * ROWW + kw + t;
                bh[ni][0] = sBh[nb]; bh[ni][1] = sBh[nb + 4];
                bl[ni][0] = sBl[nb]; bl[ni][1] = sBl[nb + 4];
            }
#pragma unroll
            for (int mi = 0; mi < 2; mi++)
#pragma unroll
                for (int ni = 0; ni < 8; ni++) {
                    mma_bf16(acc[mi][ni], ah[mi], bh[ni]);
                    mma_bf16(acc[mi][ni], ah[mi], bl[ni]);
                    mma_bf16(acc[mi][ni], al[mi], bh[ni]);
                }
        }

        // epilogue: fragments -> g_hh fp16
#pragma unroll
        for (int mi = 0; mi < 2; mi++) {
            int r0 = rowBase + wm * 32 + mi * 16 + g;
            int r1 = r0 + 8;
#pragma unroll
            for (int ni = 0; ni < 8; ni++) {
                int col = wn * 64 + ni * 8 + t * 2;
                if (r0 < N_NODES)
                    *(__half2*)&g_hh[r0 * 128 + col] =
                        __floats2half2_rn(acc[mi][ni][0], acc[mi][ni][1]);
                if (r1 < N_NODES)
                    *(__half2*)&g_hh[r1 * 128 + col] =
                        __floats2half2_rn(acc[mi][ni][2], acc[mi][ni][3]);
            }
        }
        __syncthreads();
    }
}

// ---------------- fused aggregation + bias + LayerNorm + ReLU (+ residual) ----------------
__device__ __forceinline__ float4 up4(uint2 v) {
    __half2 a = *(__half2*)&v.x;
    __half2 b = *(__half2*)&v.y;
    float2 fa = __half22float2(a);
    float2 fb = __half22float2(b);
    return make_float4(fa.x, fa.y, fb.x, fb.y);
}

// outp == nullptr: write bf16 hi/lo split images (g_ah/g_al) for the next GEMM.
// outp != nullptr: add resid, write fp32 to outp.
__global__ void __launch_bounds__(256) k_agg_ln(const float* __restrict__ bias,
                                                const float* __restrict__ gam,
                                                const float* __restrict__ bet,
                                                const float* __restrict__ resid,
                                                float* __restrict__ outp) {
    int warp = (blockIdx.x * blockDim.x + threadIdx.x) >> 5;
    int lane = threadIdx.x & 31;
    if (warp >= N_NODES) return;
    int row = warp;

    const uint2* H2 = (const uint2*)g_hh;   // 32 uint2 per row (4 halfs per lane)

    float di = g_dinv[row];
    float sl = di * di;
    float4 sv = up4(H2[row * 32 + lane]);
    float4 acc = make_float4(sv.x * sl, sv.y * sl, sv.z * sl, sv.w * sl);

    int e = g_rowstart[row];
    int e1 = g_rowstart[row + 1];
    for (; e + 4 <= e1; e += 4) {
        int s0 = g_csrsrc[e], s1 = g_csrsrc[e + 1];
        int s2 = g_csrsrc[e + 2], s3 = g_csrsrc[e + 3];
        float n0 = g_dinv[s0] * di, n1 = g_dinv[s1] * di;
        float n2 = g_dinv[s2] * di, n3 = g_dinv[s3] * di;
        uint2 r0 = H2[s0 * 32 + lane], r1 = H2[s1 * 32 + lane];
        uint2 r2 = H2[s2 * 32 + lane], r3 = H2[s3 * 32 + lane];
        float4 v0 = up4(r0), v1 = up4(r1), v2 = up4(r2), v3 = up4(r3);
        acc.x += n0 * v0.x + n1 * v1.x + n2 * v2.x + n3 * v3.x;
        acc.y += n0 * v0.y + n1 * v1.y + n2 * v2.y + n3 * v3.y;
        acc.z += n0 * v0.z + n1 * v1.z + n2 * v2.z + n3 * v3.z;
        acc.w += n0 * v0.w + n1 * v1.w + n2 * v2.w + n3 * v3.w;
    }
    for (; e < e1; e++) {
        int s0 = g_csrsrc[e];
        float n0 = g_dinv[s0] * di;
        float4 v0 = up4(H2[s0 * 32 + lane]);
        acc.x += n0 * v0.x; acc.y += n0 * v0.y;
        acc.z += n0 * v0.z; acc.w += n0 * v0.w;
    }

    float4 bb = ((const float4*)bias)[lane];
    acc.x += bb.x; acc.y += bb.y; acc.z += bb.z; acc.w += bb.w;

    float s4 = acc.x + acc.y + acc.z + acc.w;
#pragma unroll
    for (int o = 16; o; o >>= 1) s4 += __shfl_xor_sync(0xffffffffu, s4, o);
    float mu = s4 * (1.0f / 128.0f);

    float d0 = acc.x - mu, d1 = acc.y - mu, d2 = acc.z - mu, d3 = acc.w - mu;
    float q = d0 * d0 + d1 * d1 + d2 * d2 + d3 * d3;
#pragma unroll
    for (int o = 16; o; o >>= 1) q += __shfl_xor_sync(0xffffffffu, q, o);
    float inv = rsqrtf(q * (1.0f / 128.0f) + LN_EPS);

    float4 gg = ((const float4*)gam)[lane];
    float4 be = ((const float4*)bet)[lane];
    float4 o4;
    o4.x = fmaxf(d0 * inv * gg.x + be.x, 0.0f);
    o4.y = fmaxf(d1 * inv * gg.y + be.y, 0.0f);
    o4.z = fmaxf(d2 * inv * gg.z + be.z, 0.0f);
    o4.w = fmaxf(d3 * inv * gg.w + be.w, 0.0f);

    if (outp) {
        float4 rv = ((const float4*)resid)[row * 32 + lane];
        o4.x += rv.x; o4.y += rv.y; o4.z += rv.z; o4.w += rv.w;
        ((float4*)outp)[row * 32 + lane] = o4;
    } else {
        // split to bf16 hi/lo for next GEMM (row stride 64 uint32)
        __nv_bfloat16 h0 = __float2bfloat16(o4.x), h1 = __float2bfloat16(o4.y);
        __nv_bfloat16 h2 = __float2bfloat16(o4.z), h3 = __float2bfloat16(o4.w);
        __nv_bfloat16 l0 = __float2bfloat16(o4.x - __bfloat162float(h0));
        __nv_bfloat16 l1 = __float2bfloat16(o4.y - __bfloat162float(h1));
        __nv_bfloat16 l2 = __float2bfloat16(o4.z - __bfloat162float(h2));
        __nv_bfloat16 l3 = __float2bfloat16(o4.w - __bfloat162float(h3));
        int idx = row * 64 + lane * 2;
        *(uint2*)&g_ah[idx] = make_uint2(pack2(h0, h1), pack2(h2, h3));
        *(uint2*)&g_al[idx] = make_uint2(pack2(l0, l1), pack2(l2, l3));
    }
}

// ---------------- launch ----------------
extern "C" void kernel_launch(void* const* d_in, const int* in_sizes, int n_in,
                              void* d_out, int out_size) {
    const float* x   = (const float*)d_in[0];
    const int*   ei  = (const int*)d_in[1];   // int32
    const float* W1  = (const float*)d_in[2];
    const float* b1  = (const float*)d_in[3];
    const float* g1  = (const float*)d_in[4];
    const float* lb1 = (const float*)d_in[5];
    const float* W2  = (const float*)d_in[6];
    const float* b2  = (const float*)d_in[7];
    const float* g2  = (const float*)d_in[8];
    const float* lb2 = (const float*)d_in[9];
    float* out = (float*)d_out;

    static bool inited = false;
    static cudaStream_t s1;
    static cudaEvent_t evFork, evJoin;
    if (!inited) {
        cudaStreamCreate(&s1);
        cudaEventCreateWithFlags(&evFork, cudaEventDisableTiming);
        cudaEventCreateWithFlags(&evJoin, cudaEventDisableTiming);
        cudaFuncSetAttribute(k_gemm_mma, cudaFuncAttributeMaxDynamicSharedMemorySize,
                             GEMM_SMEM_BYTES);
        inited = true;
    }

    const int TB = 256;
    int gridE8 = (N_EDGES / 8 + TB - 1) / TB;    // 293 blocks, 8 edges/thread
    int gridAgg = (N_NODES * 32 + TB - 1) / TB;

    // fork: branch A (s1) = convW(+pad) + gemm1; branch B (stream 0) = CSR build
    cudaEventRecord(evFork, 0);
    cudaStreamWaitEvent(s1, evFork, 0);

    k_convW<<<dim3(32, 2), 256, 0, s1>>>(W1, W2);
    k_gemm_mma<<<GEMM_GRID, 256, GEMM_SMEM_BYTES, s1>>>(x, 0);
    cudaEventRecord(evJoin, s1);

    // CSR build: count -> scan -> fill (fill re-zeros g_cnt for next run)
    k_count<<<gridE8, TB>>>(ei);
    k_scan<<<SCAN_BLOCKS, 256>>>();
    k_fill<<<gridE8, TB>>>(ei);

    // join
    cudaStreamWaitEvent(0, evJoin, 0);

    // layer 1 epilogue -> split images; layer 2
    k_agg_ln<<<gridAgg, TB>>>(b1, g1, lb1, nullptr, nullptr);
    k_gemm_mma<<<GEMM_GRID, 256, GEMM_SMEM_BYTES>>>(nullptr, 1);
    k_agg_ln<<<gridAgg, TB>>>(b2, g2, lb2, x, out);
}

// round 10
// speedup vs baseline: 1.0086x; 1.0086x over previous
#include <cuda_runtime.h>
#include <cuda_bf16.h>
#include <cuda_fp16.h>
#include <cstdint>

#define N_NODES 50000
#define N_EDGES 600000
#define LN_EPS 1e-5f
#define NT 391            // ceil(50000/128) M-tiles
#define NROWS_PAD (NT * 128)   // 50048
#define GEMM_GRID 148
#define SCAN_BLOCKS 196   // ceil(50000/256)

// smem word layout for GEMM (uint32 units); A/B rows padded to 68 words (136 bf16)
#define ROWW 68
#define SA_HI 0
#define SA_LO 8704
#define SB_HI 17408
#define SB_LO 26112
#define GEMM_SMEM_WORDS 34816
#define GEMM_SMEM_BYTES (GEMM_SMEM_WORDS * 4)

// ---------------- device scratch ----------------
__device__ __align__(16) __half g_hh[N_NODES * 128];        // GEMM output, fp16
__device__ __align__(16) uint32_t g_ah[NROWS_PAD * 64];     // layer-1 act, bf16 hi (64 u32/row)
__device__ __align__(16) uint32_t g_al[NROWS_PAD * 64];     // layer-1 act, bf16 lo
__device__ float g_dinv[N_NODES];
__device__ __align__(16) int g_cnt[N_NODES];   // zero at load; k_fill re-zeros each run
__device__ int   g_rowstart[N_NODES + 1];
__device__ int   g_cur[N_NODES];
__device__ int   g_csrsrc[N_EDGES];
__device__ __align__(16) int g_part[SCAN_BLOCKS];
// bf16 W^T images (B layout: [n][k], linear): [layer][hi/lo]
__device__ __align__(16) uint4 g_wimg[2][2][2048];

// ---------------- CSR build ----------------
// 8 edges per thread, loads issued before the 8 non-returning REDs
__global__ void k_count(const int* __restrict__ ei) {
    int i = blockIdx.x * blockDim.x + threadIdx.x;
    const int4* D = (const int4*)(ei + N_EDGES);
    const int HALF = N_EDGES / 8;   // 75000 int4 per half
    if (i < HALF) {
        int4 d0 = D[i];
        int4 d1 = D[i + HALF];
        atomicAdd(&g_cnt[d0.x], 1);
        atomicAdd(&g_cnt[d0.y], 1);
        atomicAdd(&g_cnt[d0.z], 1);
        atomicAdd(&g_cnt[d0.w], 1);
        atomicAdd(&g_cnt[d1.x], 1);
        atomicAdd(&g_cnt[d1.y], 1);
        atomicAdd(&g_cnt[d1.z], 1);
        atomicAdd(&g_cnt[d1.w], 1);
    }
}

// per-block partial sums
__global__ void k_scan1() {
    int t = threadIdx.x, lane = t & 31, w = t >> 5;
    __shared__ int wsum[8];
    int i = blockIdx.x * 256 + t;
    int v = (i < N_NODES) ? g_cnt[i] : 0;
#pragma unroll
    for (int o = 16; o; o >>= 1) v += __shfl_xor_sync(0xffffffffu, v, o);
    if (lane == 0) wsum[w] = v;
    __syncthreads();
    if (t == 0) {
        int s = 0;
#pragma unroll
        for (int j = 0; j < 8; j++) s += wsum[j];
        g_part[blockIdx.x] = s;
    }
}

// prefix over g_part + per-node CSR init (shuffle-based)
__global__ void k_scan3() {
    __shared__ int wsum[8];
    int t = threadIdx.x, lane = t & 31, w = t >> 5;

    // cross-block offset = sum g_part[0 .. bid)  (196 values, one pass)
    int pre = 0;
    if (t < SCAN_BLOCKS && t < blockIdx.x) pre = g_part[t];
    // threads 0..255 each hold at most one partial (SCAN_BLOCKS<256)
#pragma unroll
    for (int o = 16; o; o >>= 1) pre += __shfl_xor_sync(0xffffffffu, pre, o);
    if (lane == 0) wsum[w] = pre;
    __syncthreads();
    int blockoff = 0;
#pragma unroll
    for (int j = 0; j < 8; j++) blockoff += wsum[j];
    __syncthreads();

    // intra-block inclusive scan (warp shuffle + warp offsets)
    int i = blockIdx.x * 256 + t;
    int c = (i < N_NODES) ? g_cnt[i] : 0;
    int v = c;
#pragma unroll
    for (int o = 1; o < 32; o <<= 1) {
        int n = __shfl_up_sync(0xffffffffu, v, o);
        if (lane >= o) v += n;
    }
    if (lane == 31) wsum[w] = v;
    __syncthreads();
    int woff = 0;
#pragma unroll
    for (int j = 0; j < 8; j++)
        if (j < w) woff += wsum[j];

    if (i < N_NODES) {
        int excl = blockoff + woff + v - c;
        g_rowstart[i] = excl;
        g_cur[i] = excl;
        g_dinv[i] = rsqrtf((float)c + 1.0f);
    }
    if (blockIdx.x == SCAN_BLOCKS - 1 && t == 255)
        g_rowstart[N_NODES] = blockoff + woff + v;
}

// fill CSR; also re-zeros g_cnt for the next replay (fill never reads g_cnt)
__global__ void k_fill(const int* __restrict__ ei) {
    int i = blockIdx.x * blockDim.x + threadIdx.x;
    if (i < N_NODES / 4) ((int4*)g_cnt)[i] = make_int4(0, 0, 0, 0);
    const int4* S = (const int4*)ei;
    const int4* D = (const int4*)(ei + N_EDGES);
    const int HALF = N_EDGES / 8;
    if (i < HALF) {
        int4 s0 = S[i];
        int4 d0 = D[i];
        int4 s1 = S[i + HALF];
        int4 d1 = D[i + HALF];
        g_csrsrc[atomicAdd(&g_cur[d0.x], 1)] = s0.x;
        g_csrsrc[atomicAdd(&g_cur[d0.y], 1)] = s0.y;
        g_csrsrc[atomicAdd(&g_cur[d0.z], 1)] = s0.z;
        g_csrsrc[atomicAdd(&g_cur[d0.w], 1)] = s0.w;
        g_csrsrc[atomicAdd(&g_cur[d1.x], 1)] = s1.x;
        g_csrsrc[atomicAdd(&g_cur[d1.y], 1)] = s1.y;
        g_csrsrc[atomicAdd(&g_cur[d1.z], 1)] = s1.z;
        g_csrsrc[atomicAdd(&g_cur[d1.w], 1)] = s1.w;
    }
}

// ---------------- W -> transposed bf16 hi/lo images + split-image tail pad ----------------
__global__ void k_convW(const float* __restrict__ W1, const float* __restrict__ W2) {
    int layer = blockIdx.y;
    const float* W = layer ? W2 : W1;
    __nv_bfloat16* hi = (__nv_bfloat16*)g_wimg[layer][0];
    __nv_bfloat16* lo = (__nv_bfloat16*)g_wimg[layer][1];
    for (int i = blockIdx.x * blockDim.x + threadIdx.x; i < 16384; i += blockDim.x * gridDim.x) {
        int n = i >> 7, k = i & 127;          // B[n][k] = W[k][n]
        float w = W[k * 128 + n];
        __nv_bfloat16 h = __float2bfloat16(w);
        __nv_bfloat16 l = __float2bfloat16(w - __bfloat162float(h));
        hi[n * 128 + k] = h;
        lo[n * 128 + k] = l;
    }
    // zero-pad tail rows of the split activation images (rows 50000..50047)
    if (layer == 0) {
        int base = N_NODES * 64;
        int total = (NROWS_PAD - N_NODES) * 64;   // 3072
        for (int i = blockIdx.x * blockDim.x + threadIdx.x; i < total;
             i += blockDim.x * gridDim.x / 2) {
            g_ah[base + i] = 0;
            g_al[base + i] = 0;
        }
    }
}

// ---------------- mma.sync bf16 split-precision GEMM ----------------
__device__ __forceinline__ uint32_t pack2(__nv_bfloat16 a, __nv_bfloat16 b) {
    return (uint32_t)__bfloat16_as_ushort(a) | ((uint32_t)__bfloat16_as_ushort(b) << 16);
}

__device__ __forceinline__ void mma_bf16(float* c, const uint32_t* a, const uint32_t* b) {
    asm volatile(
        "mma.sync.aligned.m16n8k16.row.col.f32.bf16.bf16.f32 "
        "{%0,%1,%2,%3}, {%4,%5,%6,%7}, {%8,%9}, {%0,%1,%2,%3};"
        : "+f"(c[0]), "+f"(c[1]), "+f"(c[2]), "+f"(c[3])
        : "r"(a[0]), "r"(a[1]), "r"(a[2]), "r"(a[3]), "r"(b[0]), "r"(b[1]));
}

// H = X @ W via D = Ah*Bh + Ah*Bl + Al*Bh; persistent CTAs over M-tiles of 128.
// layer 0: A from fp32 Xin (convert). layer 1: A from pre-split g_ah/g_al (copy).
__global__ void __launch_bounds__(256, 1) k_gemm_mma(const float* __restrict__ Xin, int layer) {
    extern __shared__ uint32_t sw[];
    uint32_t* sAh = sw + SA_HI;
    uint32_t* sAl = sw + SA_LO;
    uint32_t* sBh = sw + SB_HI;
    uint32_t* sBl = sw + SB_LO;

    const float4* X4 = (const float4*)Xin;
    int tid = threadIdx.x, wid = tid >> 5, lane = tid & 31;
    int g = lane >> 2, t = lane & 3;
    int wm = wid & 3, wn = wid >> 2;

    // stage B (W^T) hi/lo into padded smem, once
    {
        const uint4* Bh = g_wimg[layer][0];
        const uint4* Bl = g_wimg[layer][1];
#pragma unroll 4
        for (int i = tid; i < 2048; i += 256) {
            int n = i >> 4, kc = i & 15;
            *(uint4*)(sBh + n * ROWW + kc * 4) = Bh[i];
            *(uint4*)(sBl + n * ROWW + kc * 4) = Bl[i];
        }
    }
    __syncthreads();

    for (int tile = blockIdx.x; tile < NT; tile += gridDim.x) {
        int rowBase = tile * 128;

        if (layer == 0) {
            // convert A tile fp32 -> bf16 hi/lo into padded smem
#pragma unroll 4
            for (int i = tid; i < 4096; i += 256) {      // 128 rows x 32 float4
                int r = i >> 5, c = i & 31;
                int grow = rowBase + r;
                float4 v = (grow < N_NODES) ? X4[grow * 32 + c] : make_float4(0.f, 0.f, 0.f, 0.f);
                __nv_bfloat16 h0 = __float2bfloat16(v.x), h1 = __float2bfloat16(v.y);
                __nv_bfloat16 h2 = __float2bfloat16(v.z), h3 = __float2bfloat16(v.w);
                __nv_bfloat16 l0 = __float2bfloat16(v.x - __bfloat162float(h0));
                __nv_bfloat16 l1 = __float2bfloat16(v.y - __bfloat162float(h1));
                __nv_bfloat16 l2 = __float2bfloat16(v.z - __bfloat162float(h2));
                __nv_bfloat16 l3 = __float2bfloat16(v.w - __bfloat162float(h3));
                *(uint2*)(sAh + r * ROWW + c * 2) = make_uint2(pack2(h0, h1), pack2(h2, h3));
                *(uint2*)(sAl + r * ROWW + c * 2) = make_uint2(pack2(l0, l1), pack2(l2, l3));
            }
        } else {
            // copy pre-split A tile (bf16 hi/lo) into padded smem: 128 rows x 16 uint4
#pragma unroll 4
            for (int i = tid; i < 2048; i += 256) {
                int r = i >> 4, q = i & 15;
                int gi = (rowBase + r) * 16 + q;         // uint4 index (row stride 16)
                *(uint4*)(sAh + r * ROWW + q * 4) = ((const uint4*)g_ah)[gi];
                *(uint4*)(sAl + r * ROWW + q * 4) = ((const uint4*)g_al)[gi];
            }
        }
        __syncthreads();

        float acc[2][8][4];
#pragma unroll
        for (int mi = 0; mi < 2; mi++)
#pragma unroll
            for (int ni = 0; ni < 8; ni++)
#pragma unroll
                for (int j = 0; j < 4; j++) acc[mi][ni][j] = 0.0f;

#pragma unroll
        for (int ks = 0; ks < 8; ks++) {
            int kw = ks * 8;
            uint32_t ah[2][4], al[2][4];
#pragma unroll
            for (int mi = 0; mi < 2; mi++) {
                int r0 = (wm * 32 + mi * 16 + g) * ROWW + kw + t;
                int r1 = r0 + 8 * ROWW;
                ah[mi][0] = sAh[r0]; ah[mi][1] = sAh[r1];
                ah[mi][2] = sAh[r0 + 4]; ah[mi][3] = sAh[r1 + 4];
                al[mi][0] = sAl[r0]; al[mi][1] = sAl[r1];
                al[mi][2] = sAl[r0 + 4]; al[mi][3] = sAl[r1 + 4];
            }
            uint32_t bh[8][2], bl[8][2];
#pragma unroll
            for (int ni = 0; ni < 8; ni++) {
                int nb = (wn * 64 + ni * 8 + g) * ROWW + kw + t;
                bh[ni][0] = sBh[nb]; bh[ni][1] = sBh[nb + 4];
                bl[ni][0] = sBl[nb]; bl[ni][1] = sBl[nb + 4];
            }
#pragma unroll
            for (int mi = 0; mi < 2; mi++)
#pragma unroll
                for (int ni = 0; ni < 8; ni++) {
                    mma_bf16(acc[mi][ni], ah[mi], bh[ni]);
                    mma_bf16(acc[mi][ni], ah[mi], bl[ni]);
                    mma_bf16(acc[mi][ni], al[mi], bh[ni]);
                }
        }

        // epilogue: fragments -> g_hh fp16
#pragma unroll
        for (int mi = 0; mi < 2; mi++) {
            int r0 = rowBase + wm * 32 + mi * 16 + g;
            int r1 = r0 + 8;
#pragma unroll
            for (int ni = 0; ni < 8; ni++) {
                int col = wn * 64 + ni * 8 + t * 2;
                if (r0 < N_NODES)
                    *(__half2*)&g_hh[r0 * 128 + col] =
                        __floats2half2_rn(acc[mi][ni][0], acc[mi][ni][1]);
                if (r1 < N_NODES)
                    *(__half2*)&g_hh[r1 * 128 + col] =
                        __floats2half2_rn(acc[mi][ni][2], acc[mi][ni][3]);
            }
        }
        __syncthreads();
    }
}

// ---------------- fused aggregation + bias + LayerNorm + ReLU (+ residual) ----------------
__device__ __forceinline__ float4 up4(uint2 v) {
    __half2 a = *(__half2*)&v.x;
    __half2 b = *(__half2*)&v.y;
    float2 fa = __half22float2(a);
    float2 fb = __half22float2(b);
    return make_float4(fa.x, fa.y, fb.x, fb.y);
}

// outp == nullptr: write bf16 hi/lo split images (g_ah/g_al) for the next GEMM.
// outp != nullptr: add resid, write fp32 to outp.
__global__ void __launch_bounds__(256) k_agg_ln(const float* __restrict__ bias,
                                                const float* __restrict__ gam,
                                                const float* __restrict__ bet,
                                                const float* __restrict__ resid,
                                                float* __restrict__ outp) {
    int warp = (blockIdx.x * blockDim.x + threadIdx.x) >> 5;
    int lane = threadIdx.x & 31;
    if (warp >= N_NODES) return;
    int row = warp;

    const uint2* H2 = (const uint2*)g_hh;   // 32 uint2 per row (4 halfs per lane)

    float di = g_dinv[row];
    float sl = di * di;
    float4 sv = up4(H2[row * 32 + lane]);
    float4 acc = make_float4(sv.x * sl, sv.y * sl, sv.z * sl, sv.w * sl);

    int e = g_rowstart[row];
    int e1 = g_rowstart[row + 1];
    for (; e + 4 <= e1; e += 4) {
        int s0 = g_csrsrc[e], s1 = g_csrsrc[e + 1];
        int s2 = g_csrsrc[e + 2], s3 = g_csrsrc[e + 3];
        float n0 = g_dinv[s0] * di, n1 = g_dinv[s1] * di;
        float n2 = g_dinv[s2] * di, n3 = g_dinv[s3] * di;
        uint2 r0 = H2[s0 * 32 + lane], r1 = H2[s1 * 32 + lane];
        uint2 r2 = H2[s2 * 32 + lane], r3 = H2[s3 * 32 + lane];
        float4 v0 = up4(r0), v1 = up4(r1), v2 = up4(r2), v3 = up4(r3);
        acc.x += n0 * v0.x + n1 * v1.x + n2 * v2.x + n3 * v3.x;
        acc.y += n0 * v0.y + n1 * v1.y + n2 * v2.y + n3 * v3.y;
        acc.z += n0 * v0.z + n1 * v1.z + n2 * v2.z + n3 * v3.z;
        acc.w += n0 * v0.w + n1 * v1.w + n2 * v2.w + n3 * v3.w;
    }
    for (; e < e1; e++) {
        int s0 = g_csrsrc[e];
        float n0 = g_dinv[s0] * di;
        float4 v0 = up4(H2[s0 * 32 + lane]);
        acc.x += n0 * v0.x; acc.y += n0 * v0.y;
        acc.z += n0 * v0.z; acc.w += n0 * v0.w;
    }

    float4 bb = ((const float4*)bias)[lane];
    acc.x += bb.x; acc.y += bb.y; acc.z += bb.z; acc.w += bb.w;

    float s4 = acc.x + acc.y + acc.z + acc.w;
#pragma unroll
    for (int o = 16; o; o >>= 1) s4 += __shfl_xor_sync(0xffffffffu, s4, o);
    float mu = s4 * (1.0f / 128.0f);

    float d0 = acc.x - mu, d1 = acc.y - mu, d2 = acc.z - mu, d3 = acc.w - mu;
    float q = d0 * d0 + d1 * d1 + d2 * d2 + d3 * d3;
#pragma unroll
    for (int o = 16; o; o >>= 1) q += __shfl_xor_sync(0xffffffffu, q, o);
    float inv = rsqrtf(q * (1.0f / 128.0f) + LN_EPS);

    float4 gg = ((const float4*)gam)[lane];
    float4 be = ((const float4*)bet)[lane];
    float4 o4;
    o4.x = fmaxf(d0 * inv * gg.x + be.x, 0.0f);
    o4.y = fmaxf(d1 * inv * gg.y + be.y, 0.0f);
    o4.z = fmaxf(d2 * inv * gg.z + be.z, 0.0f);
    o4.w = fmaxf(d3 * inv * gg.w + be.w, 0.0f);

    if (outp) {
        float4 rv = ((const float4*)resid)[row * 32 + lane];
        o4.x += rv.x; o4.y += rv.y; o4.z += rv.z; o4.w += rv.w;
        ((float4*)outp)[row * 32 + lane] = o4;
    } else {
        // split to bf16 hi/lo for next GEMM (row stride 64 uint32)
        __nv_bfloat16 h0 = __float2bfloat16(o4.x), h1 = __float2bfloat16(o4.y);
        __nv_bfloat16 h2 = __float2bfloat16(o4.z), h3 = __float2bfloat16(o4.w);
        __nv_bfloat16 l0 = __float2bfloat16(o4.x - __bfloat162float(h0));
        __nv_bfloat16 l1 = __float2bfloat16(o4.y - __bfloat162float(h1));
        __nv_bfloat16 l2 = __float2bfloat16(o4.z - __bfloat162float(h2));
        __nv_bfloat16 l3 = __float2bfloat16(o4.w - __bfloat162float(h3));
        int idx = row * 64 + lane * 2;
        *(uint2*)&g_ah[idx] = make_uint2(pack2(h0, h1), pack2(h2, h3));
        *(uint2*)&g_al[idx] = make_uint2(pack2(l0, l1), pack2(l2, l3));
    }
}

// ---------------- launch ----------------
extern "C" void kernel_launch(void* const* d_in, const int* in_sizes, int n_in,
                              void* d_out, int out_size) {
    const float* x   = (const float*)d_in[0];
    const int*   ei  = (const int*)d_in[1];   // int32
    const float* W1  = (const float*)d_in[2];
    const float* b1  = (const float*)d_in[3];
    const float* g1  = (const float*)d_in[4];
    const float* lb1 = (const float*)d_in[5];
    const float* W2  = (const float*)d_in[6];
    const float* b2  = (const float*)d_in[7];
    const float* g2  = (const float*)d_in[8];
    const float* lb2 = (const float*)d_in[9];
    float* out = (float*)d_out;

    static bool inited = false;
    static cudaStream_t s1;
    static cudaEvent_t evFork, evJoin;
    if (!inited) {
        cudaStreamCreate(&s1);
        cudaEventCreateWithFlags(&evFork, cudaEventDisableTiming);
        cudaEventCreateWithFlags(&evJoin, cudaEventDisableTiming);
        cudaFuncSetAttribute(k_gemm_mma, cudaFuncAttributeMaxDynamicSharedMemorySize,
                             GEMM_SMEM_BYTES);
        inited = true;
    }

    const int TB = 256;
    int gridE8 = (N_EDGES / 8 + TB - 1) / TB;    // 293 blocks, 8 edges/thread
    int gridAgg = (N_NODES * 32 + TB - 1) / TB;

    // fork: branch A (s1) = convW(+pad) + gemm1; branch B (stream 0) = CSR build
    cudaEventRecord(evFork, 0);
    cudaStreamWaitEvent(s1, evFork, 0);

    k_convW<<<dim3(32, 2), 256, 0, s1>>>(W1, W2);
    k_gemm_mma<<<GEMM_GRID, 256, GEMM_SMEM_BYTES, s1>>>(x, 0);
    cudaEventRecord(evJoin, s1);

    // CSR build: count -> scan1 -> scan3 -> fill (fill re-zeros g_cnt for next run)
    k_count<<<gridE8, TB>>>(ei);
    k_scan1<<<SCAN_BLOCKS, 256>>>();
    k_scan3<<<SCAN_BLOCKS, 256>>>();
    k_fill<<<gridE8, TB>>>(ei);

    // join
    cudaStreamWaitEvent(0, evJoin, 0);

    // layer 1 epilogue -> split images; layer 2
    k_agg_ln<<<gridAgg, TB>>>(b1, g1, lb1, nullptr, nullptr);
    k_gemm_mma<<<GEMM_GRID, 256, GEMM_SMEM_BYTES>>>(nullptr, 1);
    k_agg_ln<<<gridAgg, TB>>>(b2, g2, lb2, x, out);
}